// round 3
// baseline (speedup 1.0000x reference)
#include <cuda_runtime.h>
#include <math.h>

// Problem constants
#define Bb   64
#define Cc   64
#define Ll   8192
#define Ff   4097          // rfft bins
#define NFFT 4096          // complex FFT size (L/2)
#define HID  128
#define NT   33            // f-tiles of 128 covering 4097

// ---------------- scratch (device globals; no allocations allowed) ----------
__device__ float g_fxre[Bb * Cc * Ff];          // 67 MB  rfft real (ortho)
__device__ float g_fxim[Bb * Cc * Ff];          // 67 MB  rfft imag (ortho)
__device__ float g_part[2 * Bb * HID * NT];     // per-tile partial SELU sums
__device__ float g_edge[2 * Bb * HID * 2];      // y[h,0], y[h,F-1]
__device__ float g_C[2 * Bb * 3];               // softmax coefficients C_R, C_I

// ---------------- f32x2 packed-FMA helpers (sm_103a) -------------------------
__device__ __forceinline__ unsigned long long fma2(unsigned long long a,
                                                   unsigned long long b,
                                                   unsigned long long c) {
    unsigned long long d;
    asm("fma.rn.f32x2 %0, %1, %2, %3;" : "=l"(d) : "l"(a), "l"(b), "l"(c));
    return d;
}
__device__ __forceinline__ unsigned long long bc2(float v) {
    unsigned long long d;
    asm("mov.b64 %0, {%1, %1};" : "=l"(d) : "f"(v));
    return d;
}
__device__ __forceinline__ void unpk2(unsigned long long v, float& lo, float& hi) {
    asm("mov.b64 {%0, %1}, %2;" : "=f"(lo), "=f"(hi) : "l"(v));
}

// ---------------- 4096-pt radix-4 Stockham FFT (float2 shared) ---------------
// sign = -1: forward DFT, sign = +1: unscaled inverse. 6 stages; with an even
// number of ping-pong swaps the result lands back in the A argument.
__device__ __forceinline__ void fft4096r4(float2* A, float2* B, int tid, float sign) {
#pragma unroll 1
    for (int t = 0; t < 6; t++) {
        int   s   = 1 << (2 * t);
        float th0 = sign * (6.283185307179586f / (float)(NFFT >> (2 * t)));
        __syncthreads();
#pragma unroll
        for (int i = 0; i < 4; i++) {
            int u = tid + (i << 8);
            int q = u & (s - 1);
            int p = u >> (2 * t);
            float c1, s1;
            __sincosf(th0 * (float)p, &s1, &c1);
            float c2 = c1 * c1 - s1 * s1, s2 = 2.f * c1 * s1;
            float c3 = c1 * c2 - s1 * s2, s3 = c1 * s2 + s1 * c2;
            float2 x0 = A[u], x1 = A[u + 1024], x2 = A[u + 2048], x3 = A[u + 3072];
            float apc_r = x0.x + x2.x, apc_i = x0.y + x2.y;
            float amc_r = x0.x - x2.x, amc_i = x0.y - x2.y;
            float bpd_r = x1.x + x3.x, bpd_i = x1.y + x3.y;
            float bmd_r = x1.x - x3.x, bmd_i = x1.y - x3.y;
            // js = sign*i ;  js*bmd = (-sign*bmd_i, sign*bmd_r)
            float jb_r = -sign * bmd_i, jb_i = sign * bmd_r;
            float y0r = apc_r + bpd_r, y0i = apc_i + bpd_i;
            float y1r = amc_r + jb_r,  y1i = amc_i + jb_i;
            float y2r = apc_r - bpd_r, y2i = apc_i - bpd_i;
            float y3r = amc_r - jb_r,  y3i = amc_i - jb_i;
            int o = q + 4 * s * p;
            B[o]         = make_float2(y0r, y0i);
            B[o + s]     = make_float2(y1r * c1 - y1i * s1, y1r * s1 + y1i * c1);
            B[o + 2 * s] = make_float2(y2r * c2 - y2i * s2, y2r * s2 + y2i * c2);
            B[o + 3 * s] = make_float2(y3r * c3 - y3i * s3, y3r * s3 + y3i * c3);
        }
        float2* tp = A; A = B; B = tp;
    }
    __syncthreads();
}

// ---------------- K1: forward rfft (ortho) -----------------------------------
__global__ void __launch_bounds__(256) k_fwd(const float* __restrict__ x) {
    extern __shared__ float2 smc[];
    float2* A = smc;
    float2* Bf = smc + 4096;
    int row = blockIdx.x;                    // row = b*64 + c
    int tid = threadIdx.x;

    const float2* xin = (const float2*)(x + (size_t)row * Ll);
#pragma unroll
    for (int i = 0; i < 16; i++) {
        int m = tid + (i << 8);
        A[m] = xin[m];                       // (even, odd) = packed complex
    }
    fft4096r4(A, Bf, tid, -1.0f);            // result in A

    // Hermitian unpack: X[k] = E[k] + W^k O[k], W^k = e^{-i pi k / 4096}
    const float sc = 0.011048543456039804f;  // 1/sqrt(8192)  (ortho)
    float* outre = g_fxre + (size_t)row * Ff;
    float* outim = g_fxim + (size_t)row * Ff;
    for (int k = tid; k < Ff; k += 256) {
        int    ka = k & 4095;
        int    kb = (4096 - k) & 4095;
        float2 zk = A[ka];
        float2 zm = A[kb];
        float Er = 0.5f * (zk.x + zm.x), Ei = 0.5f * (zk.y - zm.y);
        float Or = 0.5f * (zk.y + zm.y), Oi = 0.5f * (zm.x - zk.x);
        float ang = (float)k * (3.14159265358979324f / 4096.0f);
        float cw, sw;
        __sincosf(ang, &sw, &cw);            // w = (cw, -sw)
        float Xr = Er + cw * Or + sw * Oi;
        float Xi = Ei + cw * Oi - sw * Or;
        outre[k] = Xr * sc;
        outim[k] = Xi * sc;
    }
}

// ---------------- K2a: conv1 (64->128, K=3) + SELU + partial f-sum ----------
// grid (33 tiles, 64 batch, 2 paths), 256 threads.
// Packed f32x2 over h-pairs: 96 FFMA2 replace 192 FFMA per c-chunk.
__global__ void __launch_bounds__(256) k_conv(const float* __restrict__ w1R,
                                              const float* __restrict__ b1R,
                                              const float* __restrict__ w1I,
                                              const float* __restrict__ b1I) {
    __shared__ float  sh_x[16][132];         // [c-chunk][f0-1 .. f0+128]
    __shared__ float2 sh_w[16][3][64];       // [(c)][tap][(w[2h'],w[2h'+1])]

    int tile = blockIdx.x;
    int b    = blockIdx.y;
    int path = blockIdx.z;
    const float* in = (path == 0) ? g_fxre : g_fxim;
    const float* w1 = (path == 0) ? w1R : w1I;
    const float* b1 = (path == 0) ? b1R : b1I;

    int tid = threadIdx.x;
    int tx  = tid & 15;                      // f group
    int ty  = tid >> 4;                      // h group
    int f0  = tile * 128;

    unsigned long long acc[4][8];
#pragma unroll
    for (int e = 0; e < 4; e++)
#pragma unroll
        for (int j = 0; j < 8; j++) acc[e][j] = 0ull;

    for (int c0 = 0; c0 < 64; c0 += 16) {
        __syncthreads();
        for (int idx = tid; idx < 16 * 130; idx += 256) {
            int cc = idx / 130;
            int j  = idx - cc * 130;
            int f  = f0 - 1 + j;
            float v = 0.f;
            if (f >= 0 && f < Ff)
                v = in[((size_t)(b * 64 + c0 + cc)) * Ff + f];
            sh_x[cc][j] = v;
        }
        for (int idx = tid; idx < 16 * 192; idx += 256) {
            int cc = idx / 192;
            int r  = idx - cc * 192;
            int k  = r >> 6;                 // tap
            int hp = r & 63;                 // h pair
            float a = w1[((size_t)(2 * hp)     * 64 + c0 + cc) * 3 + k];
            float bq = w1[((size_t)(2 * hp + 1) * 64 + c0 + cc) * 3 + k];
            sh_w[cc][k][hp] = make_float2(a, bq);
        }
        __syncthreads();
#pragma unroll 1
        for (int cc = 0; cc < 16; cc++) {
            const float4* xr = (const float4*)&sh_x[cc][tx * 8];
            float4 v0 = xr[0];
            float4 v1 = xr[1];
            float  x8 = sh_x[cc][tx * 8 + 8];
            float  x9 = sh_x[cc][tx * 8 + 9];
            unsigned long long xb[10];
            xb[0] = bc2(v0.x); xb[1] = bc2(v0.y); xb[2] = bc2(v0.z); xb[3] = bc2(v0.w);
            xb[4] = bc2(v1.x); xb[5] = bc2(v1.y); xb[6] = bc2(v1.z); xb[7] = bc2(v1.w);
            xb[8] = bc2(x8);   xb[9] = bc2(x9);
#pragma unroll
            for (int e = 0; e < 4; e++) {
                int hp = ty * 4 + e;
                unsigned long long wa = *(const unsigned long long*)&sh_w[cc][0][hp];
                unsigned long long wb = *(const unsigned long long*)&sh_w[cc][1][hp];
                unsigned long long wc = *(const unsigned long long*)&sh_w[cc][2][hp];
#pragma unroll
                for (int ff = 0; ff < 8; ff++) {
                    unsigned long long a = acc[e][ff];
                    a = fma2(wa, xb[ff],     a);
                    a = fma2(wb, xb[ff + 1], a);
                    a = fma2(wc, xb[ff + 2], a);
                    acc[e][ff] = a;
                }
            }
        }
    }

    // bias + SELU + partial reduction over this tile's f range
    const float SC = 1.0507009873554805f, AL = 1.6732632423543772f;
#pragma unroll
    for (int e = 0; e < 4; e++) {
        int   h0 = ty * 8 + 2 * e;
        float bias0 = b1[h0];
        float bias1 = b1[h0 + 1];
        float s0 = 0.f, s1v = 0.f;
#pragma unroll
        for (int ff = 0; ff < 8; ff++) {
            int   f = f0 + tx * 8 + ff;
            float vlo, vhi;
            unpk2(acc[e][ff], vlo, vhi);
            float a0 = vlo + bias0;
            float a1 = vhi + bias1;
            float y0 = SC * ((a0 > 0.f) ? a0 : AL * expm1f(a0));
            float y1 = SC * ((a1 > 0.f) ? a1 : AL * expm1f(a1));
            if (f < Ff) {
                s0 += y0;
                s1v += y1;
                size_t eb0 = (((size_t)path * 64 + b) * 128 + h0) * 2;
                if (f == 0)      { g_edge[eb0] = y0;     g_edge[eb0 + 2] = y1; }
                if (f == Ff - 1) { g_edge[eb0 + 1] = y0; g_edge[eb0 + 3] = y1; }
            }
        }
#pragma unroll
        for (int off = 8; off >= 1; off >>= 1) {
            s0  += __shfl_xor_sync(0xffffffffu, s0, off, 16);
            s1v += __shfl_xor_sync(0xffffffffu, s1v, off, 16);
        }
        if (tx == 0) {
            size_t pb = (((size_t)path * 64 + b) * 128 + h0) * NT + tile;
            g_part[pb]      = s0;
            g_part[pb + NT] = s1v;
        }
    }
}

// ---------------- K2b: pooled conv2 + softmax --------------------------------
__global__ void __launch_bounds__(128) k_pool(const float* __restrict__ w2R,
                                              const float* __restrict__ b2R,
                                              const float* __restrict__ w2I,
                                              const float* __restrict__ b2I) {
    int bx   = blockIdx.x;
    int path = bx >> 6;
    int b    = bx & 63;
    const float* w2 = path ? w2I : w2R;
    const float* b2 = path ? b2I : b2R;
    int h = threadIdx.x;

    size_t base = ((size_t)path * 64 + b) * 128 + h;
    float  S    = 0.f;
#pragma unroll
    for (int t = 0; t < NT; t++) S += g_part[base * NT + t];
    float y0 = g_edge[base * 2 + 0];
    float yl = g_edge[base * 2 + 1];

    __shared__ float red[3][128];
#pragma unroll
    for (int n = 0; n < 3; n++) {
        const float* wp = w2 + ((size_t)n * 128 + h) * 3;
        red[n][h] = wp[0] * (S - yl) + wp[1] * S + wp[2] * (S - y0);
    }
    __syncthreads();
    for (int off = 64; off >= 1; off >>= 1) {
        if (h < off) {
#pragma unroll
            for (int n = 0; n < 3; n++) red[n][h] += red[n][h + off];
        }
        __syncthreads();
    }
    if (h == 0) {
        float z0 = red[0][0] / (float)Ff + b2[0];
        float z1 = red[1][0] / (float)Ff + b2[1];
        float z2 = red[2][0] / (float)Ff + b2[2];
        float m  = fmaxf(z0, fmaxf(z1, z2));
        float e0 = expf(z0 - m), e1 = expf(z1 - m), e2 = expf(z2 - m);
        float inv = 1.f / (e0 + e1 + e2);
        size_t cb = ((size_t)path * 64 + b) * 3;
        g_C[cb + 0] = e0 * inv;
        g_C[cb + 1] = e1 * inv;
        g_C[cb + 2] = e2 * inv;
    }
}

// ---------------- K3: Kf, spectral multiply, irfft (ortho) -------------------
__global__ void __launch_bounds__(256) k_inv(const float* __restrict__ param,
                                             float* __restrict__ out) {
    extern __shared__ float2 smc[];
    __shared__ float extra[2];               // Y[4096] (Nyquist)
    float2* A  = smc;                        // spectrum Y[0..4095]
    float2* Bf = smc + 4096;                 // packed Z then FFT ping-pong

    int row = blockIdx.x;
    int b   = row >> 6;
    int c   = row & 63;
    int tid = threadIdx.x;

    float cr0 = g_C[((size_t)0 * 64 + b) * 3 + 0];
    float cr1 = g_C[((size_t)0 * 64 + b) * 3 + 1];
    float cr2 = g_C[((size_t)0 * 64 + b) * 3 + 2];
    float ci0 = g_C[((size_t)1 * 64 + b) * 3 + 0];
    float ci1 = g_C[((size_t)1 * 64 + b) * 3 + 1];
    float ci2 = g_C[((size_t)1 * 64 + b) * 3 + 2];

    const float* fre = g_fxre + (size_t)row * Ff;
    const float* fim = g_fxim + (size_t)row * Ff;

    for (int f = tid; f < Ff; f += 256) {
        float2 w0 = *(const float2*)(param + (((size_t)0 * 64 + c) * Ff + f) * 2);
        float2 w1 = *(const float2*)(param + (((size_t)1 * 64 + c) * Ff + f) * 2);
        float2 w2 = *(const float2*)(param + (((size_t)2 * 64 + c) * Ff + f) * 2);
        float KfR = cr0 * w0.x + cr1 * w1.x + cr2 * w2.x;
        float KfI = ci0 * w0.y + ci1 * w1.y + ci2 * w2.y;
        float fr = fre[f], fi = fim[f];
        float Yr = fr * KfR - fi * KfI;
        float Yi = fr * KfI + fi * KfR;
        if (f == 0) Yi = 0.f;                // C2R discards imag of DC
        if (f < 4096) A[f] = make_float2(Yr, Yi);
        else          { extra[0] = Yr; extra[1] = 0.f; }  // ... and of Nyquist
    }
    __syncthreads();

    // Inverse packing: Z[k] = E[k] + i O[k]  (written into Bf)
    for (int k = tid; k < 4096; k += 256) {
        float2 Xk = A[k];
        float  Xmr, Xmi;
        if (k == 0) { Xmr = extra[0]; Xmi = extra[1]; }
        else        { float2 Xm = A[4096 - k]; Xmr = Xm.x; Xmi = Xm.y; }
        float Er = 0.5f * (Xk.x + Xmr), Ei = 0.5f * (Xk.y - Xmi);
        float Dr = 0.5f * (Xk.x - Xmr), Di = 0.5f * (Xk.y + Xmi);
        float ang = (float)k * (3.14159265358979324f / 4096.0f);
        float cw, sw;
        __sincosf(ang, &sw, &cw);            // W^{-k} = e^{+i ang}
        float Or = Dr * cw - Di * sw;
        float Oi = Dr * sw + Di * cw;
        Bf[k] = make_float2(Er - Oi, Ei + Or);
    }
    fft4096r4(Bf, A, tid, +1.0f);            // result lands in Bf

    const float sc = 0.022097086912079608f;  // sqrt(8192) / 4096  (ortho)
    float2* o = (float2*)(out + (size_t)row * Ll);
    for (int m = tid; m < 4096; m += 256) {
        float2 z = Bf[m];
        o[m] = make_float2(z.x * sc, z.y * sc);
    }
}

// ---------------- launch -----------------------------------------------------
extern "C" void kernel_launch(void* const* d_in, const int* in_sizes, int n_in,
                              void* d_out, int out_size) {
    const float* x   = (const float*)d_in[0];
    const float* par = (const float*)d_in[1];
    const float* wR1 = (const float*)d_in[2];
    const float* bR1 = (const float*)d_in[3];
    const float* wR2 = (const float*)d_in[4];
    const float* bR2 = (const float*)d_in[5];
    const float* wI1 = (const float*)d_in[6];
    const float* bI1 = (const float*)d_in[7];
    const float* wI2 = (const float*)d_in[8];
    const float* bI2 = (const float*)d_in[9];
    float* out = (float*)d_out;

    cudaFuncSetAttribute(k_fwd, cudaFuncAttributeMaxDynamicSharedMemorySize, 65536);
    cudaFuncSetAttribute(k_inv, cudaFuncAttributeMaxDynamicSharedMemorySize, 65536);

    k_fwd<<<Bb * Cc, 256, 65536>>>(x);
    dim3 g2(NT, Bb, 2);
    k_conv<<<g2, 256>>>(wR1, bR1, wI1, bI1);
    k_pool<<<2 * Bb, 128>>>(wR2, bR2, wI2, bI2);
    k_inv<<<Bb * Cc, 256, 65536>>>(par, out);
}

// round 7
// speedup vs baseline: 2.0321x; 2.0321x over previous
#include <cuda_runtime.h>
#include <cuda_bf16.h>
#include <math.h>
#include <cstdint>

// Problem constants
#define Bb   64
#define Cc   64
#define Ll   8192
#define Ff   4097          // rfft bins
#define NFFT 4096          // complex FFT size (L/2)
#define HID  128
#define TILE_F  64
#define NTILES  65         // 65*64 = 4160 >= 4097

// ---------------- scratch (device globals; no allocations allowed) ----------
__device__ float g_fxre[Bb * Cc * Ff];          // 67 MB  rfft real (ortho)
__device__ float g_fxim[Bb * Cc * Ff];          // 67 MB  rfft imag (ortho)
__device__ float g_S[2 * Bb * HID];             // Σ_f selu(conv1)
__device__ float g_edge[2 * Bb * HID * 2];      // y[h,0], y[h,F-1]
__device__ float g_C[2 * Bb * 3];               // softmax coefficients C_R, C_I

// ---------------- helpers ----------------------------------------------------
__device__ __forceinline__ uint32_t smem_u32(const void* p) {
    uint32_t a;
    asm("{ .reg .u64 t; cvta.to.shared.u64 t, %1; cvt.u32.u64 %0, t; }" : "=r"(a) : "l"(p));
    return a;
}
__device__ __forceinline__ void sts32(uint32_t addr, uint32_t v) {
    asm volatile("st.shared.b32 [%0], %1;" :: "r"(addr), "r"(v) : "memory");
}
__device__ __forceinline__ uint32_t lds32(uint32_t addr) {
    uint32_t v;
    asm volatile("ld.shared.b32 %0, [%1];" : "=r"(v) : "r"(addr));
    return v;
}
__device__ __forceinline__ void ldsm4(uint32_t addr, uint32_t* r) {
    asm volatile("ldmatrix.sync.aligned.m8n8.x4.shared.b16 {%0,%1,%2,%3}, [%4];"
                 : "=r"(r[0]), "=r"(r[1]), "=r"(r[2]), "=r"(r[3]) : "r"(addr));
}
__device__ __forceinline__ void mma16816(float* c, const uint32_t* a, uint32_t b0, uint32_t b1) {
    asm volatile("mma.sync.aligned.m16n8k16.row.col.f32.bf16.bf16.f32 "
                 "{%0,%1,%2,%3}, {%4,%5,%6,%7}, {%8,%9}, {%0,%1,%2,%3};"
                 : "+f"(c[0]), "+f"(c[1]), "+f"(c[2]), "+f"(c[3])
                 : "r"(a[0]), "r"(a[1]), "r"(a[2]), "r"(a[3]), "r"(b0), "r"(b1));
}

// ---------------- 4096-pt radix-2 Stockham FFT in shared memory -------------
__device__ __forceinline__ void fft4096(float* sr, float* si, float* dr, float* di,
                                        int tid, float sign) {
#pragma unroll 1
    for (int t = 0; t < 12; t++) {
        int   s      = 1 << t;
        float theta0 = sign * (6.283185307179586f / (float)(NFFT >> t));
        __syncthreads();
#pragma unroll
        for (int i = 0; i < 8; i++) {
            int u = tid + (i << 8);
            int q = u & (s - 1);
            int p = u >> t;
            float cw, sw;
            __sincosf(theta0 * (float)p, &sw, &cw);
            int   i0  = q + s * p;
            int   i1  = i0 + 2048;
            float x0r = sr[i0], x0i = si[i0];
            float x1r = sr[i1], x1i = si[i1];
            int   o0  = q + 2 * s * p;
            dr[o0] = x0r + x1r;
            di[o0] = x0i + x1i;
            float tr = x0r - x1r, ti = x0i - x1i;
            dr[o0 + s] = tr * cw - ti * sw;
            di[o0 + s] = tr * sw + ti * cw;
        }
        float* tp;
        tp = sr; sr = dr; dr = tp;
        tp = si; si = di; di = tp;
    }
    __syncthreads();
}

// ---------------- K1: forward rfft (ortho) -----------------------------------
__global__ void __launch_bounds__(256) k_fwd(const float* __restrict__ x) {
    extern __shared__ float sm[];
    float* ar = sm;
    float* ai = sm + 4096;
    float* br = sm + 8192;
    float* bi = sm + 12288;
    int row = blockIdx.x;
    int tid = threadIdx.x;

    const float2* xin = (const float2*)(x + (size_t)row * Ll);
#pragma unroll
    for (int i = 0; i < 16; i++) {
        int    m = tid + (i << 8);
        float2 v = xin[m];
        ar[m] = v.x;
        ai[m] = v.y;
    }
    fft4096(ar, ai, br, bi, tid, -1.0f);

    const float sc   = 0.011048543456039804f;   // 1/sqrt(8192)
    float* outre = g_fxre + (size_t)row * Ff;
    float* outim = g_fxim + (size_t)row * Ff;
    for (int k = tid; k < Ff; k += 256) {
        int   ka  = k & 4095;
        int   kb  = (4096 - k) & 4095;
        float zkr = ar[ka], zki = ai[ka];
        float zmr = ar[kb], zmi = ai[kb];
        float Er = 0.5f * (zkr + zmr), Ei = 0.5f * (zki - zmi);
        float Or = 0.5f * (zki + zmi), Oi = 0.5f * (zmr - zkr);
        float ang = (float)k * (3.14159265358979324f / 4096.0f);
        float cw, sw;
        __sincosf(ang, &sw, &cw);
        float Xr = Er + cw * Or + sw * Oi;
        float Xi = Ei + cw * Oi - sw * Or;
        outre[k] = Xr * sc;
        outim[k] = Xi * sc;
    }
}

// ---------------- K2a: conv1 via mma.sync bf16 + SELU + f-sum ----------------
// One CTA per (path, b). y[h, f] = sum_{tap,c} W[tap][h,c] * X[c, f+tap-1].
// Warp grid: 4 (M=32 rows each) x 2 (N=32 cols each). f-tile = 64 cols.
// smem A: [tap][h=128][c=64] bf16, row 128B, XOR-16B swizzle keyed by h&7.
// smem B: [j=66][c=64] bf16 (j = f - f0 + 1), same swizzle keyed by j&7.
#define A_TAP_BYTES 16384
#define B_BYTES     8448          // 66 * 128
__global__ void __launch_bounds__(256) k_conv(const float* __restrict__ w1R,
                                              const float* __restrict__ b1R,
                                              const float* __restrict__ w1I,
                                              const float* __restrict__ b1I) {
    extern __shared__ __align__(1024) char dynsm[];
    __shared__ float s_red[2][128];

    int bx   = blockIdx.x;
    int path = bx >> 6;
    int b    = bx & 63;
    const float* in = (path == 0) ? g_fxre : g_fxim;
    const float* w1 = (path == 0) ? w1R : w1I;
    const float* b1 = (path == 0) ? b1R : b1I;

    int tid  = threadIdx.x;
    int wid  = tid >> 5;
    int lane = tid & 31;
    int wm   = wid & 3;            // M group (32 rows)
    int wn   = wid >> 2;           // N group (32 cols)

    uint32_t A0 = smem_u32(dynsm);
    uint32_t B0 = A0 + 3 * A_TAP_BYTES;

    // ---- weights -> bf16 smem (one-time) ----
    for (int idx = tid; idx < 128 * 32; idx += 256) {
        int h  = idx >> 5;
        int cp = idx & 31;
        const float* wp = w1 + ((size_t)(h * 64 + 2 * cp)) * 3;
        float e0 = wp[0], e1 = wp[1], e2 = wp[2];
        float o0 = wp[3], o1 = wp[4], o2 = wp[5];
        uint32_t off = (uint32_t)h * 128 + (((uint32_t)cp * 4) ^ (((uint32_t)h & 7) << 4));
        __nv_bfloat162 t0 = __floats2bfloat162_rn(e0, o0);
        __nv_bfloat162 t1 = __floats2bfloat162_rn(e1, o1);
        __nv_bfloat162 t2 = __floats2bfloat162_rn(e2, o2);
        sts32(A0 + 0 * A_TAP_BYTES + off, *(uint32_t*)&t0);
        sts32(A0 + 1 * A_TAP_BYTES + off, *(uint32_t*)&t1);
        sts32(A0 + 2 * A_TAP_BYTES + off, *(uint32_t*)&t2);
    }

    // per-lane bias for the 4 row slots (mi x half)
    float bias[2][2];
#pragma unroll
    for (int mi = 0; mi < 2; mi++)
#pragma unroll
        for (int hf = 0; hf < 2; hf++)
            bias[mi][hf] = b1[wm * 32 + mi * 16 + (lane >> 2) + hf * 8];

    // B loader: thread -> (cp = tid>>3, jslot = tid&7), 9 j-iterations
    int cp = tid >> 3;
    int js = tid & 7;
    const float* r0g = in + (size_t)(b * 64 + 2 * cp) * Ff;
    const float* r1g = r0g + Ff;
    uint32_t brot = ((uint32_t)js << 4);

    float xv[9][2];
    auto fetchB = [&](int t) {
        int f0 = t * TILE_F;
#pragma unroll
        for (int i = 0; i < 9; i++) {
            int j = js + 8 * i;
            float v0 = 0.f, v1 = 0.f;
            if (j < 66) {
                int f = f0 - 1 + j;
                if (f >= 0 && f <= 4096) { v0 = r0g[f]; v1 = r1g[f]; }
            }
            xv[i][0] = v0;
            xv[i][1] = v1;
        }
    };
    auto storeB = [&](uint32_t Bbuf) {
#pragma unroll
        for (int i = 0; i < 9; i++) {
            int j = js + 8 * i;
            if (j < 66) {
                __nv_bfloat162 tv = __floats2bfloat162_rn(xv[i][0], xv[i][1]);
                sts32(Bbuf + (uint32_t)j * 128 + (((uint32_t)cp * 4) ^ brot), *(uint32_t*)&tv);
            }
        }
    };

    float s[2][2] = {{0.f, 0.f}, {0.f, 0.f}};
    const float SC = 1.0507009873554805f;
    const float SA = 1.7580993408473766f;    // SC * AL

    // A-fragment lane address pieces (constant per lane)
    uint32_t lrow_off = (uint32_t)((lane & 7) + (lane & 8));
    uint32_t kbyte_hi = (lane & 16) ? 16u : 0u;

    fetchB(0);
    storeB(B0);
    __syncthreads();

#pragma unroll 1
    for (int t = 0; t < NTILES; t++) {
        if (t + 1 < NTILES) fetchB(t + 1);   // prefetch into regs

        uint32_t Bbuf = B0 + (uint32_t)(t & 1) * B_BYTES;
        float acc[2][4][4];
#pragma unroll
        for (int mi = 0; mi < 2; mi++)
#pragma unroll
            for (int ni = 0; ni < 4; ni++)
#pragma unroll
                for (int e = 0; e < 4; e++) acc[mi][ni][e] = 0.f;

#pragma unroll
        for (int tap = 0; tap < 3; tap++) {
            uint32_t Atap = A0 + (uint32_t)tap * A_TAP_BYTES;
#pragma unroll
            for (int kf = 0; kf < 4; kf++) {
                uint32_t a[2][4];
#pragma unroll
                for (int mi = 0; mi < 2; mi++) {
                    uint32_t row  = (uint32_t)(wm * 32 + mi * 16) + lrow_off;
                    uint32_t kb   = (uint32_t)kf * 32 + kbyte_hi;
                    uint32_t addr = Atap + row * 128 + (kb ^ ((row & 7) << 4));
                    ldsm4(addr, a[mi]);
                }
                uint32_t bb[4][2];
#pragma unroll
                for (int ni = 0; ni < 4; ni++) {
                    uint32_t jrow = (uint32_t)((lane >> 2) + wn * 32 + ni * 8 + tap);
                    uint32_t cb   = (uint32_t)kf * 32 + ((uint32_t)(lane & 3)) * 4;
                    uint32_t addr = Bbuf + jrow * 128 + (cb ^ ((jrow & 7) << 4));
                    bb[ni][0] = lds32(addr);
                    bb[ni][1] = lds32(addr ^ 16u);
                }
#pragma unroll
                for (int mi = 0; mi < 2; mi++)
#pragma unroll
                    for (int ni = 0; ni < 4; ni++)
                        mma16816(acc[mi][ni], a[mi], bb[ni][0], bb[ni][1]);
            }
        }

        // epilogue: bias + SELU + row sums (+ edges)
        int  f0   = t * TILE_F;
        bool et   = (t == 0) || (t == NTILES - 1);
        bool full = (t < NTILES - 1);
#pragma unroll
        for (int mi = 0; mi < 2; mi++)
#pragma unroll
            for (int ni = 0; ni < 4; ni++)
#pragma unroll
                for (int e = 0; e < 4; e++) {
                    int f = f0 + wn * 32 + ni * 8 + (lane & 3) * 2 + (e & 1);
                    if (full || f <= 4096) {
                        int   hf = e >> 1;
                        float v  = acc[mi][ni][e] + bias[mi][hf];
                        float y  = (v > 0.f) ? SC * v : SA * (__expf(v) - 1.f);
                        s[mi][hf] += y;
                        if (et && (f == 0 || f == 4096)) {
                            int    h  = wm * 32 + mi * 16 + (lane >> 2) + hf * 8;
                            size_t eb = (((size_t)path * 64 + b) * 128 + h) * 2;
                            g_edge[eb + ((f == 0) ? 0 : 1)] = y;
                        }
                    }
                }

        if (t + 1 < NTILES) storeB(B0 + (uint32_t)((t + 1) & 1) * B_BYTES);
        __syncthreads();
    }

    // cross-lane reduce (cols live on lane%4 quads)
#pragma unroll
    for (int mi = 0; mi < 2; mi++)
#pragma unroll
        for (int hf = 0; hf < 2; hf++) {
            float v = s[mi][hf];
            v += __shfl_xor_sync(0xffffffffu, v, 1);
            v += __shfl_xor_sync(0xffffffffu, v, 2);
            s[mi][hf] = v;
        }
    if ((lane & 3) == 0) {
#pragma unroll
        for (int mi = 0; mi < 2; mi++)
#pragma unroll
            for (int hf = 0; hf < 2; hf++) {
                int h = wm * 32 + mi * 16 + (lane >> 2) + hf * 8;
                s_red[wn][h] = s[mi][hf];
            }
    }
    __syncthreads();
    if (tid < 128) {
        float S = s_red[0][tid] + s_red[1][tid];
        g_S[((size_t)path * 64 + b) * 128 + tid] = S;
    }
}

// ---------------- K2b: pooled conv2 + softmax --------------------------------
__global__ void __launch_bounds__(128) k_pool(const float* __restrict__ w2R,
                                              const float* __restrict__ b2R,
                                              const float* __restrict__ w2I,
                                              const float* __restrict__ b2I) {
    int bx   = blockIdx.x;
    int path = bx >> 6;
    int b    = bx & 63;
    const float* w2 = path ? w2I : w2R;
    const float* b2 = path ? b2I : b2R;
    int h = threadIdx.x;

    size_t base = ((size_t)path * 64 + b) * 128 + h;
    float  S    = g_S[base];
    float  y0   = g_edge[base * 2 + 0];
    float  yl   = g_edge[base * 2 + 1];

    __shared__ float red[3][128];
#pragma unroll
    for (int n = 0; n < 3; n++) {
        const float* wp = w2 + ((size_t)n * 128 + h) * 3;
        red[n][h] = wp[0] * (S - yl) + wp[1] * S + wp[2] * (S - y0);
    }
    __syncthreads();
    for (int off = 64; off >= 1; off >>= 1) {
        if (h < off) {
#pragma unroll
            for (int n = 0; n < 3; n++) red[n][h] += red[n][h + off];
        }
        __syncthreads();
    }
    if (h == 0) {
        float z0 = red[0][0] / (float)Ff + b2[0];
        float z1 = red[1][0] / (float)Ff + b2[1];
        float z2 = red[2][0] / (float)Ff + b2[2];
        float m  = fmaxf(z0, fmaxf(z1, z2));
        float e0 = expf(z0 - m), e1 = expf(z1 - m), e2 = expf(z2 - m);
        float inv = 1.f / (e0 + e1 + e2);
        size_t cb = ((size_t)path * 64 + b) * 3;
        g_C[cb + 0] = e0 * inv;
        g_C[cb + 1] = e1 * inv;
        g_C[cb + 2] = e2 * inv;
    }
}

// ---------------- K3: Kf, spectral multiply, irfft (ortho) -------------------
__global__ void __launch_bounds__(256) k_inv(const float* __restrict__ param,
                                             float* __restrict__ out) {
    extern __shared__ float sm[];
    __shared__ float extra[2];
    float* ar = sm;
    float* ai = sm + 4096;
    float* br = sm + 8192;
    float* bi = sm + 12288;

    int row = blockIdx.x;
    int b   = row >> 6;
    int c   = row & 63;
    int tid = threadIdx.x;

    float cr0 = g_C[((size_t)0 * 64 + b) * 3 + 0];
    float cr1 = g_C[((size_t)0 * 64 + b) * 3 + 1];
    float cr2 = g_C[((size_t)0 * 64 + b) * 3 + 2];
    float ci0 = g_C[((size_t)1 * 64 + b) * 3 + 0];
    float ci1 = g_C[((size_t)1 * 64 + b) * 3 + 1];
    float ci2 = g_C[((size_t)1 * 64 + b) * 3 + 2];

    const float* fre = g_fxre + (size_t)row * Ff;
    const float* fim = g_fxim + (size_t)row * Ff;

    for (int f = tid; f < Ff; f += 256) {
        float2 w0 = *(const float2*)(param + (((size_t)0 * 64 + c) * Ff + f) * 2);
        float2 w1 = *(const float2*)(param + (((size_t)1 * 64 + c) * Ff + f) * 2);
        float2 w2 = *(const float2*)(param + (((size_t)2 * 64 + c) * Ff + f) * 2);
        float KfR = cr0 * w0.x + cr1 * w1.x + cr2 * w2.x;
        float KfI = ci0 * w0.y + ci1 * w1.y + ci2 * w2.y;
        float fr = fre[f], fi = fim[f];
        float Yr = fr * KfR - fi * KfI;
        float Yi = fr * KfI + fi * KfR;
        if (f == 0) Yi = 0.f;
        if (f < 4096) { ar[f] = Yr; ai[f] = Yi; }
        else          { extra[0] = Yr; extra[1] = 0.f; }
    }
    __syncthreads();

    for (int k = tid; k < 4096; k += 256) {
        float Xkr = ar[k], Xki = ai[k];
        float Xmr, Xmi;
        if (k == 0) { Xmr = extra[0]; Xmi = extra[1]; }
        else        { Xmr = ar[4096 - k]; Xmi = ai[4096 - k]; }
        float Er = 0.5f * (Xkr + Xmr), Ei = 0.5f * (Xki - Xmi);
        float Dr = 0.5f * (Xkr - Xmr), Di = 0.5f * (Xki + Xmi);
        float ang = (float)k * (3.14159265358979324f / 4096.0f);
        float cw, sw;
        __sincosf(ang, &sw, &cw);
        float Or = Dr * cw - Di * sw;
        float Oi = Dr * sw + Di * cw;
        br[k] = Er - Oi;
        bi[k] = Ei + Or;
    }
    fft4096(br, bi, ar, ai, tid, +1.0f);

    const float sc = 0.022097086912079608f;
    float2* o = (float2*)(out + (size_t)row * Ll);
    for (int m = tid; m < 4096; m += 256)
        o[m] = make_float2(br[m] * sc, bi[m] * sc);
}

// ---------------- launch -----------------------------------------------------
extern "C" void kernel_launch(void* const* d_in, const int* in_sizes, int n_in,
                              void* d_out, int out_size) {
    const float* x   = (const float*)d_in[0];
    const float* par = (const float*)d_in[1];
    const float* wR1 = (const float*)d_in[2];
    const float* bR1 = (const float*)d_in[3];
    const float* wR2 = (const float*)d_in[4];
    const float* bR2 = (const float*)d_in[5];
    const float* wI1 = (const float*)d_in[6];
    const float* bI1 = (const float*)d_in[7];
    const float* wI2 = (const float*)d_in[8];
    const float* bI2 = (const float*)d_in[9];
    float* out = (float*)d_out;

    const int convSmem = 3 * A_TAP_BYTES + 2 * B_BYTES;  // 66048
    cudaFuncSetAttribute(k_fwd,  cudaFuncAttributeMaxDynamicSharedMemorySize, 65536);
    cudaFuncSetAttribute(k_inv,  cudaFuncAttributeMaxDynamicSharedMemorySize, 65536);
    cudaFuncSetAttribute(k_conv, cudaFuncAttributeMaxDynamicSharedMemorySize, convSmem);

    k_fwd<<<Bb * Cc, 256, 65536>>>(x);
    k_conv<<<2 * Bb, 256, convSmem>>>(wR1, bR1, wI1, bI1);
    k_pool<<<2 * Bb, 128>>>(wR2, bR2, wI2, bI2);
    k_inv<<<Bb * Cc, 256, 65536>>>(par, out);
}

// round 8
// speedup vs baseline: 3.1265x; 1.5386x over previous
#include <cuda_runtime.h>
#include <cuda_bf16.h>
#include <math.h>
#include <cstdint>

// Problem constants
#define Bb   64
#define Cc   64
#define Ll   8192
#define Ff   4097          // rfft bins
#define NFFT 4096          // complex FFT size (L/2)
#define HID  128
#define TILE_F  64
#define NTILES  65         // 65*64 = 4160 >= 4097
#define SEG     5
#define TPS     13         // tiles per segment (5*13 = 65)

// ---------------- scratch (device globals; no allocations allowed) ----------
__device__ float g_fxre[Bb * Cc * Ff];          // 67 MB  rfft real (ortho)
__device__ float g_fxim[Bb * Cc * Ff];          // 67 MB  rfft imag (ortho)
__device__ float g_Spart[SEG * 2 * Bb * HID];   // per-segment SELU sums
__device__ float g_edge[2 * Bb * HID * 2];      // y[h,0], y[h,F-1]
__device__ float g_C[2 * Bb * 3];               // softmax coefficients C_R, C_I

// ---------------- helpers ----------------------------------------------------
__device__ __forceinline__ uint32_t smem_u32(const void* p) {
    uint32_t a;
    asm("{ .reg .u64 t; cvta.to.shared.u64 t, %1; cvt.u32.u64 %0, t; }" : "=r"(a) : "l"(p));
    return a;
}
__device__ __forceinline__ void sts32(uint32_t addr, uint32_t v) {
    asm volatile("st.shared.b32 [%0], %1;" :: "r"(addr), "r"(v) : "memory");
}
__device__ __forceinline__ uint32_t lds32(uint32_t addr) {
    uint32_t v;
    asm volatile("ld.shared.b32 %0, [%1];" : "=r"(v) : "r"(addr));
    return v;
}
__device__ __forceinline__ void ldsm4(uint32_t addr, uint32_t* r) {
    asm volatile("ldmatrix.sync.aligned.m8n8.x4.shared.b16 {%0,%1,%2,%3}, [%4];"
                 : "=r"(r[0]), "=r"(r[1]), "=r"(r[2]), "=r"(r[3]) : "r"(addr));
}
__device__ __forceinline__ void mma16816(float* c, const uint32_t* a, uint32_t b0, uint32_t b1) {
    asm volatile("mma.sync.aligned.m16n8k16.row.col.f32.bf16.bf16.f32 "
                 "{%0,%1,%2,%3}, {%4,%5,%6,%7}, {%8,%9}, {%0,%1,%2,%3};"
                 : "+f"(c[0]), "+f"(c[1]), "+f"(c[2]), "+f"(c[3])
                 : "r"(a[0]), "r"(a[1]), "r"(a[2]), "r"(a[3]), "r"(b0), "r"(b1));
}
__device__ __forceinline__ float2 cmul(float2 a, float2 b) {
    return make_float2(a.x * b.x - a.y * b.y, a.x * b.y + a.y * b.x);
}
__device__ __forceinline__ int fpad(int i) { return i + (i >> 4); }

// ---------------- 16-point DFT in registers ----------------------------------
__device__ __forceinline__ void dft16(float2* x, float sgn) {
    const float C1 = 0.9238795325112867f, S1 = 0.3826834323650898f, Rq = 0.7071067811865476f;
    float2 g[16];
#pragma unroll
    for (int j1 = 0; j1 < 4; j1++) {
        float2 a = x[j1], b = x[j1 + 4], c = x[j1 + 8], d = x[j1 + 12];
        float t0r = a.x + c.x, t0i = a.y + c.y;
        float t1r = a.x - c.x, t1i = a.y - c.y;
        float t2r = b.x + d.x, t2i = b.y + d.y;
        float t3r = -sgn * (b.y - d.y), t3i = sgn * (b.x - d.x);
        g[j1 * 4 + 0] = make_float2(t0r + t2r, t0i + t2i);
        g[j1 * 4 + 1] = make_float2(t1r + t3r, t1i + t3i);
        g[j1 * 4 + 2] = make_float2(t0r - t2r, t0i - t2i);
        g[j1 * 4 + 3] = make_float2(t1r - t3r, t1i - t3i);
    }
    float2 u1 = make_float2(C1,  sgn * S1), u2 = make_float2(Rq,  sgn * Rq);
    float2 u3 = make_float2(S1,  sgn * C1), u4 = make_float2(0.f, sgn);
    float2 u6 = make_float2(-Rq, sgn * Rq), u9 = make_float2(-C1, -sgn * S1);
    g[5]  = cmul(g[5],  u1); g[6]  = cmul(g[6],  u2); g[7]  = cmul(g[7],  u3);
    g[9]  = cmul(g[9],  u2); g[10] = cmul(g[10], u4); g[11] = cmul(g[11], u6);
    g[13] = cmul(g[13], u3); g[14] = cmul(g[14], u6); g[15] = cmul(g[15], u9);
#pragma unroll
    for (int k1 = 0; k1 < 4; k1++) {
        float2 a = g[k1], b = g[4 + k1], c = g[8 + k1], d = g[12 + k1];
        float t0r = a.x + c.x, t0i = a.y + c.y;
        float t1r = a.x - c.x, t1i = a.y - c.y;
        float t2r = b.x + d.x, t2i = b.y + d.y;
        float t3r = -sgn * (b.y - d.y), t3i = sgn * (b.x - d.x);
        x[k1]      = make_float2(t0r + t2r, t0i + t2i);
        x[k1 + 4]  = make_float2(t1r + t3r, t1i + t3i);
        x[k1 + 8]  = make_float2(t0r - t2r, t0i - t2i);
        x[k1 + 12] = make_float2(t1r - t3r, t1i - t3i);
    }
}

// ---------------- 4096-pt radix-16 Stockham FFT, in place --------------------
// A is padded: logical index i lives at A[fpad(i)]. 3 stages, 6 syncs total.
__device__ __forceinline__ void fft4096_r16(float2* A, int tid, float sgn) {
#pragma unroll
    for (int t = 0; t < 3; t++) {
        int sh = 4 * t;
        int s  = 1 << sh;
        float2 x[16];
#pragma unroll
        for (int j = 0; j < 16; j++) x[j] = A[fpad(tid + (j << 8))];
        __syncthreads();
        dft16(x, sgn);
        if (t < 2) {
            int   p  = tid >> sh;
            float th = sgn * 0.0015339807878856412f * (float)(p << sh);  // 2π/4096
            float c1v, s1v, c4v, s4v;
            __sincosf(th, &s1v, &c1v);
            __sincosf(4.f * th, &s4v, &c4v);
            float2 W1 = make_float2(c1v, s1v), W4 = make_float2(c4v, s4v);
            float2 W2 = cmul(W1, W1), W3 = cmul(W2, W1);
            float2 W8 = cmul(W4, W4), W12 = cmul(W8, W4);
            x[1]  = cmul(x[1],  W1);  x[2]  = cmul(x[2],  W2);  x[3]  = cmul(x[3],  W3);
            x[4]  = cmul(x[4],  W4);
            x[5]  = cmul(x[5],  cmul(W4, W1));
            x[6]  = cmul(x[6],  cmul(W4, W2));
            x[7]  = cmul(x[7],  cmul(W4, W3));
            x[8]  = cmul(x[8],  W8);
            x[9]  = cmul(x[9],  cmul(W8, W1));
            x[10] = cmul(x[10], cmul(W8, W2));
            x[11] = cmul(x[11], cmul(W8, W3));
            x[12] = cmul(x[12], W12);
            x[13] = cmul(x[13], cmul(W12, W1));
            x[14] = cmul(x[14], cmul(W12, W2));
            x[15] = cmul(x[15], cmul(W12, W3));
        }
        int q    = tid & (s - 1);
        int base = q + ((tid >> sh) << (sh + 4));
#pragma unroll
        for (int k = 0; k < 16; k++) A[fpad(base + (k << sh))] = x[k];
        __syncthreads();
    }
}

#define FFT_SMEM ((4096 + 256) * sizeof(float2))   // 34816 B

// ---------------- K1: forward rfft (ortho) -----------------------------------
__global__ void __launch_bounds__(256) k_fwd(const float* __restrict__ x) {
    extern __shared__ float2 smc[];
    int row = blockIdx.x;
    int tid = threadIdx.x;

    const float2* xin = (const float2*)(x + (size_t)row * Ll);
#pragma unroll
    for (int i = 0; i < 16; i++) {
        int m = tid + (i << 8);
        smc[fpad(m)] = xin[m];               // (even, odd) packed complex
    }
    __syncthreads();
    fft4096_r16(smc, tid, -1.0f);

    // Hermitian unpack: X[k] = E[k] + W^k O[k], W^k = e^{-i pi k / 4096}
    const float sc = 0.011048543456039804f;  // 1/sqrt(8192)
    float* outre = g_fxre + (size_t)row * Ff;
    float* outim = g_fxim + (size_t)row * Ff;
    for (int k = tid; k < Ff; k += 256) {
        int    ka = k & 4095;
        int    kb = (4096 - k) & 4095;
        float2 zk = smc[fpad(ka)];
        float2 zm = smc[fpad(kb)];
        float Er = 0.5f * (zk.x + zm.x), Ei = 0.5f * (zk.y - zm.y);
        float Or = 0.5f * (zk.y + zm.y), Oi = 0.5f * (zm.x - zk.x);
        float ang = (float)k * (3.14159265358979324f / 4096.0f);
        float cw, sw;
        __sincosf(ang, &sw, &cw);
        float Xr = Er + cw * Or + sw * Oi;
        float Xi = Ei + cw * Oi - sw * Or;
        outre[k] = Xr * sc;
        outim[k] = Xi * sc;
    }
}

// ---------------- K2a: conv1 via mma.sync bf16 + SELU + f-sum ----------------
#define A_TAP_BYTES 16384
#define B_BYTES     8448          // 66 * 128
__global__ void __launch_bounds__(256, 3) k_conv(const float* __restrict__ w1R,
                                                 const float* __restrict__ b1R,
                                                 const float* __restrict__ w1I,
                                                 const float* __restrict__ b1I) {
    extern __shared__ __align__(1024) char dynsm[];
    __shared__ float s_red[2][128];

    int seg  = blockIdx.x;
    int b    = blockIdx.y;
    int path = blockIdx.z;
    const float* in = (path == 0) ? g_fxre : g_fxim;
    const float* w1 = (path == 0) ? w1R : w1I;
    const float* b1 = (path == 0) ? b1R : b1I;

    int tid  = threadIdx.x;
    int wid  = tid >> 5;
    int lane = tid & 31;
    int wm   = wid & 3;            // M group (32 rows)
    int wn   = wid >> 2;           // N group (32 cols)

    int t_beg = seg * TPS;
    int t_end = t_beg + TPS;       // 5*13 = 65 exactly

    uint32_t A0 = smem_u32(dynsm);
    uint32_t B0 = A0 + 3 * A_TAP_BYTES;

    // ---- weights -> bf16 smem (one-time) ----
    for (int idx = tid; idx < 128 * 32; idx += 256) {
        int h  = idx >> 5;
        int cp = idx & 31;
        const float* wp = w1 + ((size_t)(h * 64 + 2 * cp)) * 3;
        float e0 = wp[0], e1 = wp[1], e2 = wp[2];
        float o0 = wp[3], o1 = wp[4], o2 = wp[5];
        uint32_t off = (uint32_t)h * 128 + (((uint32_t)cp * 4) ^ (((uint32_t)h & 7) << 4));
        __nv_bfloat162 t0 = __floats2bfloat162_rn(e0, o0);
        __nv_bfloat162 t1 = __floats2bfloat162_rn(e1, o1);
        __nv_bfloat162 t2 = __floats2bfloat162_rn(e2, o2);
        sts32(A0 + 0 * A_TAP_BYTES + off, *(uint32_t*)&t0);
        sts32(A0 + 1 * A_TAP_BYTES + off, *(uint32_t*)&t1);
        sts32(A0 + 2 * A_TAP_BYTES + off, *(uint32_t*)&t2);
    }

    float bias[2][2];
#pragma unroll
    for (int mi = 0; mi < 2; mi++)
#pragma unroll
        for (int hf = 0; hf < 2; hf++)
            bias[mi][hf] = b1[wm * 32 + mi * 16 + (lane >> 2) + hf * 8];

    // B loader: thread -> (cp = tid>>3, jslot = tid&7), 9 j-iterations
    int cp = tid >> 3;
    int js = tid & 7;
    const float* r0g = in + (size_t)(b * 64 + 2 * cp) * Ff;
    const float* r1g = r0g + Ff;
    uint32_t brot = ((uint32_t)js << 4);

    uint32_t xv[9];
    auto fetchB = [&](int t) {
        int f0 = t * TILE_F;
#pragma unroll
        for (int i = 0; i < 9; i++) {
            int j = js + 8 * i;
            float v0 = 0.f, v1 = 0.f;
            if (j < 66) {
                int f = f0 - 1 + j;
                if (f >= 0 && f <= 4096) { v0 = r0g[f]; v1 = r1g[f]; }
            }
            __nv_bfloat162 tv = __floats2bfloat162_rn(v0, v1);
            xv[i] = *(uint32_t*)&tv;
        }
    };
    auto storeB = [&](uint32_t Bbuf) {
#pragma unroll
        for (int i = 0; i < 9; i++) {
            int j = js + 8 * i;
            if (j < 66)
                sts32(Bbuf + (uint32_t)j * 128 + (((uint32_t)cp * 4) ^ brot), xv[i]);
        }
    };

    float s[2][2] = {{0.f, 0.f}, {0.f, 0.f}};
    const float SC = 1.0507009873554805f;
    const float SA = 1.7580993408473766f;    // SC * AL

    uint32_t lrow_off = (uint32_t)((lane & 7) + (lane & 8));
    uint32_t kbyte_hi = (lane & 16) ? 16u : 0u;

    fetchB(t_beg);
    storeB(B0 + (uint32_t)(t_beg & 1) * B_BYTES);
    __syncthreads();

#pragma unroll 1
    for (int t = t_beg; t < t_end; t++) {
        if (t + 1 < t_end) fetchB(t + 1);    // prefetch into regs

        uint32_t Bbuf = B0 + (uint32_t)(t & 1) * B_BYTES;
        float acc[2][4][4];
#pragma unroll
        for (int mi = 0; mi < 2; mi++)
#pragma unroll
            for (int ni = 0; ni < 4; ni++)
#pragma unroll
                for (int e = 0; e < 4; e++) acc[mi][ni][e] = 0.f;

#pragma unroll
        for (int tap = 0; tap < 3; tap++) {
            uint32_t Atap = A0 + (uint32_t)tap * A_TAP_BYTES;
#pragma unroll
            for (int kf = 0; kf < 4; kf++) {
                uint32_t a[2][4];
#pragma unroll
                for (int mi = 0; mi < 2; mi++) {
                    uint32_t row  = (uint32_t)(wm * 32 + mi * 16) + lrow_off;
                    uint32_t kb   = (uint32_t)kf * 32 + kbyte_hi;
                    uint32_t addr = Atap + row * 128 + (kb ^ ((row & 7) << 4));
                    ldsm4(addr, a[mi]);
                }
                uint32_t bb[4][2];
#pragma unroll
                for (int ni = 0; ni < 4; ni++) {
                    uint32_t jrow = (uint32_t)((lane >> 2) + wn * 32 + ni * 8 + tap);
                    uint32_t cb   = (uint32_t)kf * 32 + ((uint32_t)(lane & 3)) * 4;
                    uint32_t addr = Bbuf + jrow * 128 + (cb ^ ((jrow & 7) << 4));
                    bb[ni][0] = lds32(addr);
                    bb[ni][1] = lds32(addr ^ 16u);
                }
#pragma unroll
                for (int mi = 0; mi < 2; mi++)
#pragma unroll
                    for (int ni = 0; ni < 4; ni++)
                        mma16816(acc[mi][ni], a[mi], bb[ni][0], bb[ni][1]);
            }
        }

        // epilogue: bias + SELU + row sums (+ edges)
        int  f0   = t * TILE_F;
        bool et   = (t == 0) || (t == NTILES - 1);
        bool full = (t < NTILES - 1);
#pragma unroll
        for (int mi = 0; mi < 2; mi++)
#pragma unroll
            for (int ni = 0; ni < 4; ni++)
#pragma unroll
                for (int e = 0; e < 4; e++) {
                    int f = f0 + wn * 32 + ni * 8 + (lane & 3) * 2 + (e & 1);
                    if (full || f <= 4096) {
                        int   hf = e >> 1;
                        float v  = acc[mi][ni][e] + bias[mi][hf];
                        float y  = (v > 0.f) ? SC * v : SA * (__expf(v) - 1.f);
                        s[mi][hf] += y;
                        if (et && (f == 0 || f == 4096)) {
                            int    h  = wm * 32 + mi * 16 + (lane >> 2) + hf * 8;
                            size_t eb = (((size_t)path * 64 + b) * 128 + h) * 2;
                            g_edge[eb + ((f == 0) ? 0 : 1)] = y;
                        }
                    }
                }

        if (t + 1 < t_end) storeB(B0 + (uint32_t)((t + 1) & 1) * B_BYTES);
        __syncthreads();
    }

    // cross-lane reduce (cols live on lane%4 quads)
#pragma unroll
    for (int mi = 0; mi < 2; mi++)
#pragma unroll
        for (int hf = 0; hf < 2; hf++) {
            float v = s[mi][hf];
            v += __shfl_xor_sync(0xffffffffu, v, 1);
            v += __shfl_xor_sync(0xffffffffu, v, 2);
            s[mi][hf] = v;
        }
    if ((lane & 3) == 0) {
#pragma unroll
        for (int mi = 0; mi < 2; mi++)
#pragma unroll
            for (int hf = 0; hf < 2; hf++) {
                int h = wm * 32 + mi * 16 + (lane >> 2) + hf * 8;
                s_red[wn][h] = s[mi][hf];
            }
    }
    __syncthreads();
    if (tid < 128) {
        float S = s_red[0][tid] + s_red[1][tid];
        g_Spart[(((size_t)seg * 2 + path) * 64 + b) * 128 + tid] = S;
    }
}

// ---------------- K2b: pooled conv2 + softmax --------------------------------
__global__ void __launch_bounds__(128) k_pool(const float* __restrict__ w2R,
                                              const float* __restrict__ b2R,
                                              const float* __restrict__ w2I,
                                              const float* __restrict__ b2I) {
    int bx   = blockIdx.x;
    int path = bx >> 6;
    int b    = bx & 63;
    const float* w2 = path ? w2I : w2R;
    const float* b2 = path ? b2I : b2R;
    int h = threadIdx.x;

    size_t base = ((size_t)path * 64 + b) * 128 + h;
    float  S    = 0.f;
#pragma unroll
    for (int sg = 0; sg < SEG; sg++)
        S += g_Spart[(((size_t)sg * 2 + path) * 64 + b) * 128 + h];
    float y0 = g_edge[base * 2 + 0];
    float yl = g_edge[base * 2 + 1];

    __shared__ float red[3][128];
#pragma unroll
    for (int n = 0; n < 3; n++) {
        const float* wp = w2 + ((size_t)n * 128 + h) * 3;
        red[n][h] = wp[0] * (S - yl) + wp[1] * S + wp[2] * (S - y0);
    }
    __syncthreads();
    for (int off = 64; off >= 1; off >>= 1) {
        if (h < off) {
#pragma unroll
            for (int n = 0; n < 3; n++) red[n][h] += red[n][h + off];
        }
        __syncthreads();
    }
    if (h == 0) {
        float z0 = red[0][0] / (float)Ff + b2[0];
        float z1 = red[1][0] / (float)Ff + b2[1];
        float z2 = red[2][0] / (float)Ff + b2[2];
        float m  = fmaxf(z0, fmaxf(z1, z2));
        float e0 = expf(z0 - m), e1 = expf(z1 - m), e2 = expf(z2 - m);
        float inv = 1.f / (e0 + e1 + e2);
        size_t cb = ((size_t)path * 64 + b) * 3;
        g_C[cb + 0] = e0 * inv;
        g_C[cb + 1] = e1 * inv;
        g_C[cb + 2] = e2 * inv;
    }
}

// ---------------- K3: Kf, spectral multiply, irfft (ortho) -------------------
__global__ void __launch_bounds__(256) k_inv(const float* __restrict__ param,
                                             float* __restrict__ out) {
    extern __shared__ float2 smc[];
    __shared__ float extra;                  // Y[4096] real (Nyquist)

    int row = blockIdx.x;
    int b   = row >> 6;
    int c   = row & 63;
    int tid = threadIdx.x;

    float cr0 = g_C[((size_t)0 * 64 + b) * 3 + 0];
    float cr1 = g_C[((size_t)0 * 64 + b) * 3 + 1];
    float cr2 = g_C[((size_t)0 * 64 + b) * 3 + 2];
    float ci0 = g_C[((size_t)1 * 64 + b) * 3 + 0];
    float ci1 = g_C[((size_t)1 * 64 + b) * 3 + 1];
    float ci2 = g_C[((size_t)1 * 64 + b) * 3 + 2];

    const float* fre = g_fxre + (size_t)row * Ff;
    const float* fim = g_fxim + (size_t)row * Ff;

    // spectral multiply: Y[f] = fx[f] * Kf[f]
    for (int f = tid; f < Ff; f += 256) {
        float2 w0 = *(const float2*)(param + (((size_t)0 * 64 + c) * Ff + f) * 2);
        float2 w1 = *(const float2*)(param + (((size_t)1 * 64 + c) * Ff + f) * 2);
        float2 w2 = *(const float2*)(param + (((size_t)2 * 64 + c) * Ff + f) * 2);
        float KfR = cr0 * w0.x + cr1 * w1.x + cr2 * w2.x;
        float KfI = ci0 * w0.y + ci1 * w1.y + ci2 * w2.y;
        float fr = fre[f], fi = fim[f];
        float Yr = fr * KfR - fi * KfI;
        float Yi = fr * KfI + fi * KfR;
        if (f == 0) Yi = 0.f;                // C2R discards imag of DC
        if (f < 4096) smc[fpad(f)] = make_float2(Yr, Yi);
        else          extra = Yr;            // ... and of Nyquist
    }
    __syncthreads();

    // In-place pairwise inverse packing: Z[k] = E[k] + i O[k]
    // Pair (k, 4096-k): one thread owns both; one sincos serves both.
#pragma unroll 1
    for (int i = 0; i < 8; i++) {
        int k = tid + (i << 8);
        if (k == 0) {
            float2 Y0  = smc[fpad(0)];
            float  Nyq = extra;
            float Er = 0.5f * (Y0.x + Nyq), Dr = 0.5f * (Y0.x - Nyq);
            float Ei = 0.5f * Y0.y,         Di = 0.5f * Y0.y;
            smc[fpad(0)] = make_float2(Er - Di, Ei + Dr);
            float2 Yc = smc[fpad(2048)];     // self-paired bin
            smc[fpad(2048)] = make_float2(Yc.x, -Yc.y);
        } else {
            int    m  = 4096 - k;
            float2 Xk = smc[fpad(k)];
            float2 Xm = smc[fpad(m)];
            float Er = 0.5f * (Xk.x + Xm.x), Ei = 0.5f * (Xk.y - Xm.y);
            float Dr = 0.5f * (Xk.x - Xm.x), Di = 0.5f * (Xk.y + Xm.y);
            float ang = (float)k * (3.14159265358979324f / 4096.0f);
            float cw, sw;
            __sincosf(ang, &sw, &cw);        // W^{-k} = e^{+i ang}
            float Or = Dr * cw - Di * sw;
            float Oi = Dr * sw + Di * cw;
            smc[fpad(k)] = make_float2(Er - Oi, Ei + Or);
            smc[fpad(m)] = make_float2(Er + Oi, Or - Ei);
        }
    }
    __syncthreads();

    fft4096_r16(smc, tid, +1.0f);            // unscaled inverse, in place

    const float sc = 0.022097086912079608f;  // sqrt(8192) / 4096
    float2* o = (float2*)(out + (size_t)row * Ll);
#pragma unroll
    for (int i = 0; i < 16; i++) {
        int m = tid + (i << 8);
        float2 z = smc[fpad(m)];
        o[m] = make_float2(z.x * sc, z.y * sc);
    }
}

// ---------------- launch -----------------------------------------------------
extern "C" void kernel_launch(void* const* d_in, const int* in_sizes, int n_in,
                              void* d_out, int out_size) {
    const float* x   = (const float*)d_in[0];
    const float* par = (const float*)d_in[1];
    const float* wR1 = (const float*)d_in[2];
    const float* bR1 = (const float*)d_in[3];
    const float* wR2 = (const float*)d_in[4];
    const float* bR2 = (const float*)d_in[5];
    const float* wI1 = (const float*)d_in[6];
    const float* bI1 = (const float*)d_in[7];
    const float* wI2 = (const float*)d_in[8];
    const float* bI2 = (const float*)d_in[9];
    float* out = (float*)d_out;

    const int convSmem = 3 * A_TAP_BYTES + 2 * B_BYTES;  // 66048
    cudaFuncSetAttribute(k_conv, cudaFuncAttributeMaxDynamicSharedMemorySize, convSmem);

    k_fwd<<<Bb * Cc, 256, FFT_SMEM>>>(x);
    dim3 gconv(SEG, Bb, 2);
    k_conv<<<gconv, 256, convSmem>>>(wR1, bR1, wI1, bI1);
    k_pool<<<2 * Bb, 128>>>(wR2, bR2, wI2, bI2);
    k_inv<<<Bb * Cc, 256, FFT_SMEM>>>(par, out);
}